// round 8
// baseline (speedup 1.0000x reference)
#include <cuda_runtime.h>

// Problem constants
#define BB 32
#define TT 24
#define NN 325
#define DD 64
#define NHEAD 8
#define DHEAD 8

#define NB 4                  // nodes per CTA
#define MROWS (NB * TT)       // 96 rows
#define NTILES ((NN + NB - 1) / NB)   // 82
#define NTHREADS 256

// smem float offsets (114688 B -> 2 CTAs/SM)
#define XB_OFF 0                      // 96*64 (X -> attention O)
#define QB_OFF 6144                   // Q -> FC1 hidden H
#define KB_OFF 12288
#define VB_OFF 18432
#define WP_OFF 24576                  // split-pair weight slot (4096 floats)
#define SMEM_FLOATS 28672
#define SMEM_BYTES (SMEM_FLOATS * 4)

typedef unsigned long long ull;

__device__ __forceinline__ ull ffma2(ull a, ull b, ull c) {
    ull d;
    asm("fma.rn.f32x2 %0, %1, %2, %3;" : "=l"(d) : "l"(a), "l"(b), "l"(c));
    return d;
}
__device__ __forceinline__ float2 unpack2(ull v) {
    float2 r;
    asm("mov.b64 {%0, %1}, %2;" : "=f"(r.x), "=f"(r.y) : "l"(v));
    return r;
}

// Rotation layout: logical chunk k4 (0..15) of row r lives at memory chunk
// (k4 + rot(r)) & 15, rot(r) = (r/6) & 1.  The two half-warps of a GEMM warp
// (row-groups rg, rg+1) then touch bank-disjoint A addresses, while W reads
// stay identical across half-warps (broadcast).
__device__ __forceinline__ int rot_of_row(int r) { return (r / 6) & 1; }

// ---------------------------------------------------------------------------
// Stage a 64x64 weight matrix into split-pair form. For k-group k4 (0..15):
//   block = Wp + k4*256
//   block[cg*4 + {0..3}]       = {W[4k4][c0],  W[4k4+1][c0],  W[4k4][c1],  W[4k4+1][c1]}
//   block[64 + cg*4 + {0..3}]  = cols 4cg+2,4cg+3 of k-pair (4k4, 4k4+1)
//   block[128 ...]             = same for k-pair (4k4+2, 4k4+3)
// ---------------------------------------------------------------------------
__device__ __forceinline__ void load_weight_pairs(float* __restrict__ Wp,
                                                  const float* __restrict__ Wg,
                                                  int tid) {
#pragma unroll
    for (int it = 0; it < 2; ++it) {
        int idx = tid + it * NTHREADS;        // 512 tasks: p(32) x cg(16)
        int p = idx >> 4;                     // k-pair index 0..31
        int cg = idx & 15;
        float4 g0 = *(const float4*)(Wg + (2 * p) * DD + cg * 4);
        float4 g1 = *(const float4*)(Wg + (2 * p + 1) * DD + cg * 4);
        int k4 = p >> 1;
        int sub = (p & 1) ? 128 : 0;
        float* dst = Wp + (k4 << 8) + sub + cg * 4;
        *(float4*)(dst)      = make_float4(g0.x, g1.x, g0.y, g1.y);
        *(float4*)(dst + 64) = make_float4(g0.z, g1.z, g0.w, g1.w);
    }
}

// ---------------------------------------------------------------------------
// GEMM core: C[96x64] = A[96x64] @ W[64x64].
// Thread tile 6 rows x 4 cols; 16 row-groups x 16 col-groups = 256 threads.
// Iterates logical k-groups; A chunk address = ((k + rot) & 15) * 4.
// W block offset k*256 is compile-time; identical across the warp (broadcast).
// acc[i][j] packs {even-k sum, odd-k sum}; final = lo + hi.
// ---------------------------------------------------------------------------
__device__ __forceinline__ void gemm_core(const float* __restrict__ As,
                                          const float* __restrict__ Wp,
                                          ull acc[6][4], int r0, int cg, int rot) {
#pragma unroll
    for (int i = 0; i < 6; ++i)
#pragma unroll
        for (int j = 0; j < 4; ++j) acc[i][j] = 0ull;

    const float* a0 = As + r0 * DD;
    const float* wcg = Wp + cg * 4;

#pragma unroll 4
    for (int k = 0; k < 16; ++k) {
        const float* wb = wcg + (k << 8);
        ulonglong2 w0lo = *(const ulonglong2*)(wb);         // pair p0, cols 0,1
        ulonglong2 w0hi = *(const ulonglong2*)(wb + 64);    // pair p0, cols 2,3
        ulonglong2 w1lo = *(const ulonglong2*)(wb + 128);   // pair p1, cols 0,1
        ulonglong2 w1hi = *(const ulonglong2*)(wb + 192);   // pair p1, cols 2,3
        const int ao = ((k + rot) & 15) << 2;
#pragma unroll
        for (int i = 0; i < 6; ++i) {
            ulonglong2 a = *(const ulonglong2*)(a0 + i * DD + ao);
            // a.x = {x[4k], x[4k+1]}, a.y = {x[4k+2], x[4k+3]}
            acc[i][0] = ffma2(a.x, w0lo.x, acc[i][0]);
            acc[i][1] = ffma2(a.x, w0lo.y, acc[i][1]);
            acc[i][2] = ffma2(a.x, w0hi.x, acc[i][2]);
            acc[i][3] = ffma2(a.x, w0hi.y, acc[i][3]);
            acc[i][0] = ffma2(a.y, w1lo.x, acc[i][0]);
            acc[i][1] = ffma2(a.y, w1lo.y, acc[i][1]);
            acc[i][2] = ffma2(a.y, w1hi.x, acc[i][2]);
            acc[i][3] = ffma2(a.y, w1hi.y, acc[i][3]);
        }
    }
}

// Epilogue -> rotated smem buffer, bias + ReLU.
__device__ __forceinline__ void gemm_to_smem(const float* __restrict__ As,
                                             const float* __restrict__ Wp,
                                             const float* __restrict__ bias,
                                             float* __restrict__ outs, int tid) {
    const int rg = tid >> 4;
    const int cg = tid & 15;
    const int r0 = rg * 6;
    const int rot = rg & 1;
    ull acc[6][4];
    gemm_core(As, Wp, acc, r0, cg, rot);
    float4 bb = *(const float4*)(bias + cg * 4);
    const int sc = ((cg + rot) & 15) << 2;   // rotated store chunk offset
#pragma unroll
    for (int i = 0; i < 6; ++i) {
        float2 s0 = unpack2(acc[i][0]);
        float2 s1 = unpack2(acc[i][1]);
        float2 s2 = unpack2(acc[i][2]);
        float2 s3 = unpack2(acc[i][3]);
        float4 r;
        r.x = fmaxf(s0.x + s0.y + bb.x, 0.f);
        r.y = fmaxf(s1.x + s1.y + bb.y, 0.f);
        r.z = fmaxf(s2.x + s2.y + bb.z, 0.f);
        r.w = fmaxf(s3.x + s3.y + bb.w, 0.f);
        *(float4*)(outs + (r0 + i) * DD + sc) = r;
    }
}

// Epilogue -> global Y (final layer), bias, no ReLU, node guard.
__device__ __forceinline__ void gemm_to_global(const float* __restrict__ As,
                                               const float* __restrict__ Wp,
                                               const float* __restrict__ bias,
                                               float* __restrict__ Y,
                                               int b, int n0, int tid) {
    const int rg = tid >> 4;
    const int cg = tid & 15;
    const int r0 = rg * 6;
    const int rot = rg & 1;
    ull acc[6][4];
    gemm_core(As, Wp, acc, r0, cg, rot);
    float4 bb = *(const float4*)(bias + cg * 4);
#pragma unroll
    for (int i = 0; i < 6; ++i) {
        int row = r0 + i;
        int node = row / TT;
        int t = row - node * TT;
        int n = n0 + node;
        if (n < NN) {
            float2 s0 = unpack2(acc[i][0]);
            float2 s1 = unpack2(acc[i][1]);
            float2 s2 = unpack2(acc[i][2]);
            float2 s3 = unpack2(acc[i][3]);
            float4 r = make_float4(s0.x + s0.y + bb.x, s1.x + s1.y + bb.y,
                                   s2.x + s2.y + bb.z, s3.x + s3.y + bb.w);
            *(float4*)(Y + ((size_t)(b * TT + t) * NN + n) * DD + cg * 4) = r;
        }
    }
}

// ---------------------------------------------------------------------------
// Attention: one thread per (node, head, t-triple): 4*8*8 = 256 tasks.
// K/V rows loaded once per 3 queries; K/V reads are warp-broadcast per head.
// No max-subtraction (softmax shift-invariant; masked terms exactly 0).
// ---------------------------------------------------------------------------
__device__ __forceinline__ void attention(const float* __restrict__ Qs,
                                          const float* __restrict__ Ks,
                                          const float* __restrict__ Vs,
                                          float* __restrict__ Os,
                                          int tid) {
    const float scale = 0.3535533905932738f;  // 1/sqrt(8)
    const int node = tid >> 6;
    const int h = (tid >> 3) & 7;
    const int tg = tid & 7;
    const int tbase = tg * 3;
    const int rbase = node * TT;
    const int ch = 2 * h;

    // Q/O rows rbase + tg*3 + {0,1,2} share rot = (tg>>1) & 1
    const int rotq = (tg >> 1) & 1;
    const int qc1 = ((ch + rotq) & 15) << 2;
    const int qc2 = ((ch + 1 + rotq) & 15) << 2;

    float q[3][8];
    float o[3][8];
    float sum[3];
#pragma unroll
    for (int i = 0; i < 3; ++i) {
        const float* qr = Qs + (rbase + tbase + i) * DD;
        float4 a = *(const float4*)(qr + qc1);
        float4 c = *(const float4*)(qr + qc2);
        q[i][0] = a.x * scale; q[i][1] = a.y * scale;
        q[i][2] = a.z * scale; q[i][3] = a.w * scale;
        q[i][4] = c.x * scale; q[i][5] = c.y * scale;
        q[i][6] = c.z * scale; q[i][7] = c.w * scale;
        sum[i] = 0.0f;
#pragma unroll
        for (int j = 0; j < 8; ++j) o[i][j] = 0.0f;
    }

#pragma unroll
    for (int j = 0; j < 4; ++j) {                 // s = 6j + u; rows share rot = j&1
        const int rots = j & 1;
        const int c1 = ((ch + rots) & 15) << 2;
        const int c2 = ((ch + 1 + rots) & 15) << 2;
#pragma unroll
        for (int u = 0; u < 6; ++u) {
            int s = 6 * j + u;
            const float* kr = Ks + (rbase + s) * DD;
            const float* vr = Vs + (rbase + s) * DD;
            float4 k0 = *(const float4*)(kr + c1);
            float4 k1 = *(const float4*)(kr + c2);
            float4 v0 = *(const float4*)(vr + c1);
            float4 v1 = *(const float4*)(vr + c2);
#pragma unroll
            for (int i = 0; i < 3; ++i) {
                float dot = q[i][0] * k0.x;
                dot = fmaf(q[i][1], k0.y, dot);
                dot = fmaf(q[i][2], k0.z, dot);
                dot = fmaf(q[i][3], k0.w, dot);
                dot = fmaf(q[i][4], k1.x, dot);
                dot = fmaf(q[i][5], k1.y, dot);
                dot = fmaf(q[i][6], k1.z, dot);
                dot = fmaf(q[i][7], k1.w, dot);
                float e = (s >= tbase + i) ? __expf(dot) : 0.0f;
                sum[i] += e;
                o[i][0] = fmaf(e, v0.x, o[i][0]);
                o[i][1] = fmaf(e, v0.y, o[i][1]);
                o[i][2] = fmaf(e, v0.z, o[i][2]);
                o[i][3] = fmaf(e, v0.w, o[i][3]);
                o[i][4] = fmaf(e, v1.x, o[i][4]);
                o[i][5] = fmaf(e, v1.y, o[i][5]);
                o[i][6] = fmaf(e, v1.z, o[i][6]);
                o[i][7] = fmaf(e, v1.w, o[i][7]);
            }
        }
    }

#pragma unroll
    for (int i = 0; i < 3; ++i) {
        float inv = 1.0f / sum[i];
        float* orow = Os + (rbase + tbase + i) * DD;
        *(float4*)(orow + qc1) =
            make_float4(o[i][0] * inv, o[i][1] * inv, o[i][2] * inv, o[i][3] * inv);
        *(float4*)(orow + qc2) =
            make_float4(o[i][4] * inv, o[i][5] * inv, o[i][6] * inv, o[i][7] * inv);
    }
}

// ---------------------------------------------------------------------------
// Fused kernel: one CTA per (batch, 4-node tile); 2 CTAs/SM.
// ---------------------------------------------------------------------------
__global__ void __launch_bounds__(NTHREADS, 2)
temporal_attention_fused(const float* __restrict__ X,
                         const float* __restrict__ Wq, const float* __restrict__ bq,
                         const float* __restrict__ Wk, const float* __restrict__ bk,
                         const float* __restrict__ Wv, const float* __restrict__ bv,
                         const float* __restrict__ Wf1, const float* __restrict__ bf1,
                         const float* __restrict__ Wf2, const float* __restrict__ bf2,
                         float* __restrict__ Y) {
    extern __shared__ float smem[];
    float* Xb = smem + XB_OFF;   // X, later attention output O
    float* Qb = smem + QB_OFF;   // Q, later FC1 hidden H
    float* Kb = smem + KB_OFF;
    float* Vb = smem + VB_OFF;
    float* Wp = smem + WP_OFF;

    const int tid = threadIdx.x;
    const int n0 = blockIdx.x * NB;
    const int b = blockIdx.y;

    // Load X tile into rotated layout; zero-fill out-of-range nodes.
#pragma unroll 2
    for (int i = tid; i < MROWS * 16; i += NTHREADS) {
        int row = i >> 4;
        int f4 = i & 15;
        int node = row / TT;
        int t = row - node * TT;
        int n = n0 + node;
        float4 v = make_float4(0.f, 0.f, 0.f, 0.f);
        if (n < NN)
            v = *(const float4*)(X + ((size_t)(b * TT + t) * NN + n) * DD + f4 * 4);
        int sc = ((f4 + rot_of_row(row)) & 15) << 2;
        *(float4*)(Xb + row * DD + sc) = v;
    }
    load_weight_pairs(Wp, Wq, tid);
    __syncthreads();

    gemm_to_smem(Xb, Wp, bq, Qb, tid);        // q = relu(X@Wq + bq)
    __syncthreads();
    load_weight_pairs(Wp, Wk, tid);
    __syncthreads();
    gemm_to_smem(Xb, Wp, bk, Kb, tid);        // k
    __syncthreads();
    load_weight_pairs(Wp, Wv, tid);
    __syncthreads();
    gemm_to_smem(Xb, Wp, bv, Vb, tid);        // v
    __syncthreads();

    load_weight_pairs(Wp, Wf1, tid);          // stage Wf1 while attention runs
    attention(Qb, Kb, Vb, Xb, tid);           // O overwrites X buffer
    __syncthreads();

    gemm_to_smem(Xb, Wp, bf1, Qb, tid);       // h = relu(O@Wf1 + bf1) -> Q buffer
    __syncthreads();
    load_weight_pairs(Wp, Wf2, tid);
    __syncthreads();
    gemm_to_global(Qb, Wp, bf2, Y, b, n0, tid);  // y = h@Wf2 + bf2
}

// ---------------------------------------------------------------------------
// kernel_launch: inputs per metadata order:
// 0=X 1=STE(unused) 2=Wq 3=bq 4=Wk 5=bk 6=Wv 7=bv 8=Wf1 9=bf1 10=Wf2 11=bf2
// ---------------------------------------------------------------------------
extern "C" void kernel_launch(void* const* d_in, const int* in_sizes, int n_in,
                              void* d_out, int out_size) {
    const float* X   = (const float*)d_in[0];
    const float* Wq  = (const float*)d_in[2];
    const float* bq  = (const float*)d_in[3];
    const float* Wk  = (const float*)d_in[4];
    const float* bk  = (const float*)d_in[5];
    const float* Wv  = (const float*)d_in[6];
    const float* bv  = (const float*)d_in[7];
    const float* Wf1 = (const float*)d_in[8];
    const float* bf1 = (const float*)d_in[9];
    const float* Wf2 = (const float*)d_in[10];
    const float* bf2 = (const float*)d_in[11];
    float* Y = (float*)d_out;

    cudaFuncSetAttribute(temporal_attention_fused,
                         cudaFuncAttributeMaxDynamicSharedMemorySize, SMEM_BYTES);

    dim3 grid(NTILES, BB);
    temporal_attention_fused<<<grid, NTHREADS, SMEM_BYTES>>>(
        X, Wq, bq, Wk, bk, Wv, bv, Wf1, bf1, Wf2, bf2, Y);
}